// round 11
// baseline (speedup 1.0000x reference)
#include <cuda_runtime.h>
#include <cuda_fp16.h>
#include <cstdint>

#define FEAT 1184
#define BATCH 131072

// Pre-scaled fp16 weights: fp16(c*W)
__device__ __align__(16) __half g_wh[87040];

__global__ void prep_w(const float* __restrict__ w) {
    int i = blockIdx.x * 256 + threadIdx.x;
    if (i >= 87040) return;
    float c = (i < 65536) ? 0.0625f
            : (i < 81920) ? 0.08838834764831843f
            : (i < 86016) ? 0.125f
            : 0.17677669529663687f;
    g_wh[i] = __float2half_rn(w[i] * c);
}

static __device__ __forceinline__ uint32_t s2u(const void* p) {
    return (uint32_t)__cvta_generic_to_shared(p);
}
static __device__ __forceinline__ uint32_t sw128(uint32_t off) {
    return off ^ ((off >> 3) & 0x70);
}
static __device__ __forceinline__ uint32_t packh2(float a, float b) {
    __half2 h = __floats2half2_rn(a, b);
    return *(uint32_t*)&h;
}
static __device__ __forceinline__ void ldsm4(uint32_t* r, uint32_t addr) {
    asm volatile("ldmatrix.sync.aligned.m8n8.x4.shared.b16 {%0,%1,%2,%3}, [%4];"
                 : "=r"(r[0]), "=r"(r[1]), "=r"(r[2]), "=r"(r[3]) : "r"(addr));
}
static __device__ __forceinline__ void mma16816(float* c, const uint32_t* a,
                                                const uint32_t* b) {
    asm volatile("mma.sync.aligned.m16n8k16.row.col.f32.f16.f16.f32 "
                 "{%0,%1,%2,%3}, {%4,%5,%6,%7}, {%8,%9}, {%0,%1,%2,%3};"
                 : "+f"(c[0]), "+f"(c[1]), "+f"(c[2]), "+f"(c[3])
                 : "r"(a[0]), "r"(a[1]), "r"(a[2]), "r"(a[3]),
                   "r"(b[0]), "r"(b[1]));
}

// y[r, v] = sum_k A[r,k] * fp16(c*W[v,k]),  r = b*D + i,
//   A[r,k] = x[b*FEAT + xo + k*D + i]
// D>1 tiles are batch-aligned: tile m covers batches [m*NBT, m*NBT+NBT),
// rows MROWS = NBT*D <= 128, MMA padded to 128 rows.
template<int MUL, int D, int BN, int NT, int WNW, int NBT, int OCC>
__global__ void __launch_bounds__(NT, OCC) eqlin(
    const float* __restrict__ x, float* __restrict__ out,
    int xo, int wo, int mtiles)
{
    constexpr int KC      = (MUL < 64) ? MUL : 64;
    constexpr int NCH     = MUL / KC;
    constexpr int KSTEPS  = KC / 16;
    constexpr int OCTS    = KC / 8;
    constexpr int WSZ     = NCH * BN * 128;      // resident W bytes
    constexpr int A_OFF   = WSZ;
    constexpr int NABUF   = (D == 1) ? 2 : 1;
    constexpr int STG_OFF = A_OFF + NABUF * 16384;
    constexpr int STRIDE  = KC * D + 4;          // floats; == 4 (mod 32)
    constexpr int F4PB    = KC * D / 4;          // float4 per batch per chunk
    constexpr int STGSZ   = NBT * STRIDE * 4;    // bytes per staging buffer
    constexpr int NSBUF   = (NCH > 1) ? 2 : 1;   // staging depth
    // epilogue staging (D>1): two batch-aligned passes
    constexpr int BP      = (NBT + 1) / 2;       // batches per pass
    constexpr int RP      = BP * D;              // rows per pass
    constexpr int PITCH   = BN + 2;              // floats; even, ==2 (mod 32)
    constexpr int EPI_OFF = STG_OFF + NSBUF * STGSZ;
    constexpr int F4B     = BN * D / 4;          // float4 per batch (output)
    constexpr int WARPS   = NT / 32;
    constexpr int WN      = BN / WNW;            // == 32 in all configs
    constexpr int NT8     = WN / 8;
    constexpr int MWARPS  = WARPS / WNW;
    constexpr int MT      = 128 / MWARPS / 16;   // m16 frags per warp
    constexpr int TASKS   = (128 * OCTS) / NT;

    extern __shared__ char smem[];
    const uint32_t sb = s2u(smem);
    const int tid  = threadIdx.x;
    const int lane = tid & 31;
    const int warp = tid >> 5;
    const int wm   = warp / WNW;
    const int wn   = warp % WNW;

    // ---- Resident W (fp16), chunk-major 128B rows, SW128 ----
    for (int e = tid; e < BN * (MUL / 8); e += NT) {
        int v = e / (MUL / 8), o = e % (MUL / 8);
        int k = o * 8;
        uint4 hv = *(const uint4*)(g_wh + wo + (size_t)v * MUL + k);
        uint32_t off = (uint32_t)((k / KC) * (BN * 128) + v * 128 + (k % KC) * 2);
        *(uint4*)(smem + sw128(off)) = hv;
    }

    float acc[MT][NT8][4];
    float st[(D == 1) ? TASKS : 1][8];

    // cp.async: contiguous float4 span of chunk c of tile m into buffer buf
    auto stage_ld = [&](int m, int c, int buf) {
        int B0 = m * NBT;
        for (int e = tid; e < NBT * F4PB; e += NT) {
            int bl = e / F4PB, f = e - bl * F4PB;
            int b = B0 + bl;
            if (b >= BATCH) b = BATCH - 1;
            const float* src = x + (size_t)b * FEAT + xo + c * (KC * D) + f * 4;
            uint32_t dst = sb + STG_OFF + (uint32_t)buf * STGSZ +
                           (uint32_t)(bl * STRIDE + f * 4) * 4;
            asm volatile("cp.async.cg.shared.global [%0], [%1], 16;"
                         :: "r"(dst), "l"(src) : "memory");
        }
        asm volatile("cp.async.commit_group;" ::: "memory");
    };

    // D>1: strided LDS from staging -> fp16 -> swizzled A (rows batch-local)
    auto conv_chunk = [&](int buf) {
        const float* stgF = (const float*)(smem + STG_OFF + buf * STGSZ);
#pragma unroll
        for (int t = 0; t < TASKS; t++) {
            int e = tid + t * NT;
            int rl = e & 127, o = e >> 7;
            int bl = rl / D;
            if (bl > NBT - 1) bl = NBT - 1;        // padding rows
            int i = rl - bl * D;
            const float* s = stgF + bl * STRIDE + (o * 8) * D + i;
            float v[8];
#pragma unroll
            for (int j = 0; j < 8; j++) v[j] = s[j * D];
            uint32_t p0 = packh2(v[0], v[1]), p1 = packh2(v[2], v[3]);
            uint32_t p2 = packh2(v[4], v[5]), p3 = packh2(v[6], v[7]);
            *(uint4*)(smem + A_OFF + sw128((uint32_t)(rl * 128 + o * 16))) =
                make_uint4(p0, p1, p2, p3);
        }
    };

    // D==1: coalesced LDG float4 -> regs -> swizzled A
    auto ldg_chunk = [&](int m, int c) {
#pragma unroll
        for (int t = 0; t < TASKS; t++) {
            int e = tid + t * NT;
            int rl = e & 127, o = e >> 7;
            const float* xp = x + (size_t)(m * 128 + rl) * FEAT + xo + c * KC + o * 8;
            float4 q0 = *(const float4*)xp;
            float4 q1 = *(const float4*)(xp + 4);
            st[t][0] = q0.x; st[t][1] = q0.y; st[t][2] = q0.z; st[t][3] = q0.w;
            st[t][4] = q1.x; st[t][5] = q1.y; st[t][6] = q1.z; st[t][7] = q1.w;
        }
    };
    auto sts_chunk = [&](int buf) {
#pragma unroll
        for (int t = 0; t < TASKS; t++) {
            int e = tid + t * NT;
            int rl = e & 127, o = e >> 7;
            uint32_t p0 = packh2(st[t][0], st[t][1]), p1 = packh2(st[t][2], st[t][3]);
            uint32_t p2 = packh2(st[t][4], st[t][5]), p3 = packh2(st[t][6], st[t][7]);
            *(uint4*)(smem + A_OFF + buf * 16384 +
                      sw128((uint32_t)(rl * 128 + o * 16))) = make_uint4(p0, p1, p2, p3);
        }
    };

    auto mma_chunk = [&](uint32_t aoff, int c) {
        const int q = lane >> 3, p = lane & 7;
#pragma unroll
        for (int s = 0; s < KSTEPS; s++) {
            uint32_t af[MT][4];
#pragma unroll
            for (int mt = 0; mt < MT; mt++) {
                uint32_t row = (uint32_t)(wm * (MT * 16) + mt * 16 + (q & 1) * 8 + p);
                uint32_t kb  = (uint32_t)(s * 32 + (q >> 1) * 16);
                ldsm4(af[mt], sb + aoff + sw128(row * 128 + kb));
            }
#pragma unroll
            for (int ntp = 0; ntp < NT8 / 2; ntp++) {
                uint32_t vv = (uint32_t)(wn * WN + ntp * 16 + (q >> 1) * 8 + p);
                uint32_t kb = (uint32_t)(s * 32 + (q & 1) * 16);
                uint32_t bh[4];
                ldsm4(bh, sb + (uint32_t)(c * (BN * 128)) + sw128(vv * 128 + kb));
#pragma unroll
                for (int t2 = 0; t2 < 2; t2++)
#pragma unroll
                    for (int mt = 0; mt < MT; mt++)
                        mma16816(acc[mt][ntp * 2 + t2], af[mt], bh + 2 * t2);
            }
        }
    };

    auto zero_acc = [&]() {
#pragma unroll
        for (int mt = 0; mt < MT; mt++)
#pragma unroll
            for (int nt = 0; nt < NT8; nt++)
#pragma unroll
                for (int j = 0; j < 4; j++) acc[mt][nt][j] = 0.0f;
    };

    // D>1 epilogue: acc -> smem [row][v] (2 batch-aligned passes) -> float4 STG
    auto epi_d = [&](int m) {
        const int B0 = m * NBT;
        float* epiS = (float*)(smem + EPI_OFF);
        const int rb = wm * (MT * 16) + (lane >> 2);
        const int cb = wn * WN + 2 * (lane & 3);
#pragma unroll 1
        for (int p = 0; p < 2; p++) {
            const int lo = p * RP;
            __syncthreads();     // prior readers of epiS / A done
#pragma unroll
            for (int mt = 0; mt < MT; mt++) {
#pragma unroll
                for (int half = 0; half < 2; half++) {
                    int r = rb + mt * 16 + half * 8 - lo;
                    if (r >= 0 && r < RP) {
                        float* row = epiS + r * PITCH + cb;
#pragma unroll
                        for (int nt = 0; nt < NT8; nt++) {
                            row[nt * 8]     = acc[mt][nt][half * 2];
                            row[nt * 8 + 1] = acc[mt][nt][half * 2 + 1];
                        }
                    }
                }
            }
            __syncthreads();
            int pnb = NBT - p * BP; if (pnb > BP) pnb = BP;
            int nf4 = pnb * F4B;
            for (int e = tid; e < nf4; e += NT) {
                int bl = e / F4B;                  // const divisor
                int q  = e - bl * F4B;
                int b  = B0 + p * BP + bl;
                if (b < BATCH) {
                    int j0 = q * 4;
                    int v = j0 / D;                // const divisor
                    int i = j0 - v * D;
                    const float* base = epiS + bl * D * PITCH;
                    float4 val;
                    val.x = base[i * PITCH + v]; if (++i == D) { i = 0; v++; }
                    val.y = base[i * PITCH + v]; if (++i == D) { i = 0; v++; }
                    val.z = base[i * PITCH + v]; if (++i == D) { i = 0; v++; }
                    val.w = base[i * PITCH + v];
                    *(float4*)(out + (size_t)b * FEAT + xo + j0) = val;
                }
            }
        }
    };

    if (D == 1) {
        ldg_chunk(blockIdx.x, 0);
        __syncthreads();                       // W visible
        int g = 0;
        for (int m = blockIdx.x; m < mtiles; m += gridDim.x) {
            zero_acc();
#pragma unroll 1
            for (int c = 0; c < NCH; c++) {
                int buf = g & 1;
                sts_chunk(buf);
                __syncthreads();
                int cn = c + 1, mn = m;
                if (cn == NCH) { cn = 0; mn = m + gridDim.x; }
                if (mn < mtiles) ldg_chunk(mn, cn);
                mma_chunk((uint32_t)(A_OFF + buf * 16384), c);
                g++;
            }
            // direct epilogue (contiguous float2 per row)
            const int row_base = m * 128 + wm * (MT * 16) + (lane >> 2);
            const int col_base = wn * WN + 2 * (lane & 3);
#pragma unroll
            for (int mt = 0; mt < MT; mt++)
#pragma unroll
                for (int nt = 0; nt < NT8; nt++) {
                    float* a = acc[mt][nt];
                    int cc = col_base + nt * 8;
                    int r1 = row_base + mt * 16;
                    *(float2*)(out + (size_t)r1 * FEAT + xo + cc) =
                        make_float2(a[0], a[1]);
                    *(float2*)(out + (size_t)(r1 + 8) * FEAT + xo + cc) =
                        make_float2(a[2], a[3]);
                }
        }
    } else if (NCH == 1) {
        // single chunk per tile; single staging buffer, overlap next-tile load
        if (blockIdx.x < mtiles) stage_ld(blockIdx.x, 0, 0);
        for (int m = blockIdx.x; m < mtiles; m += gridDim.x) {
            zero_acc();
            asm volatile("cp.async.wait_group 0;" ::: "memory");
            __syncthreads();                   // staging + W visible; A free
            conv_chunk(0);
            __syncthreads();                   // A ready; staging reusable
            int mn = m + gridDim.x;
            if (mn < mtiles) stage_ld(mn, 0, 0);   // overlaps MMA + epilogue
            mma_chunk((uint32_t)A_OFF, 0);
            epi_d(m);
        }
    } else {
        // NCH==2 (block1): depth-2 staging pipeline across chunks
        int ms = blockIdx.x, cs = 0;
        auto stage_adv = [&](int buf) {
            if (ms < mtiles) stage_ld(ms, cs, buf);
            else asm volatile("cp.async.commit_group;" ::: "memory");
            if (++cs == NCH) { cs = 0; ms += gridDim.x; }
        };
        stage_adv(0);
        stage_adv(1);
        int g = 0;
        for (int m = blockIdx.x; m < mtiles; m += gridDim.x) {
            zero_acc();
#pragma unroll 1
            for (int c = 0; c < NCH; c++) {
                asm volatile("cp.async.wait_group 1;" ::: "memory");
                __syncthreads();               // staging g visible; A free
                conv_chunk(g & 1);
                __syncthreads();               // A ready; staging buf reusable
                stage_adv(g & 1);              // chunk g+2 into same buf
                mma_chunk((uint32_t)A_OFF, c);
                g++;
            }
            epi_d(m);
        }
    }
}

extern "C" void kernel_launch(void* const* d_in, const int* in_sizes, int n_in,
                              void* d_out, int out_size)
{
    const float* x = (const float*)d_in[0];
    const float* w = (const float*)d_in[1];
    float* out = (float*)d_out;

    prep_w<<<(87040 + 255) / 256, 256>>>(w);

    // smem budgets (mirror template math)
    constexpr int SM0 = 4 * 256 * 128 + 2 * 16384;                      // 163840
    constexpr int SM1 = 32768 + 16384 + 2 * (42 * 196 * 4) + 63 * 130 * 4; // 147768
    constexpr int SM2 = 8192 + 16384 + (25 * 324 * 4) + 65 * 66 * 4;    // 74136
    constexpr int SM3 = 4096 + 16384 + (18 * 228 * 4) + 63 * 34 * 4;    // 45464

    cudaFuncSetAttribute(eqlin<256, 1, 256, 512, 8, 128, 1>, cudaFuncAttributeMaxDynamicSharedMemorySize, SM0);
    cudaFuncSetAttribute(eqlin<128, 3, 128, 512, 4, 42, 1>,  cudaFuncAttributeMaxDynamicSharedMemorySize, SM1);
    cudaFuncSetAttribute(eqlin<64, 5, 64, 256, 2, 25, 3>,    cudaFuncAttributeMaxDynamicSharedMemorySize, SM2);
    cudaFuncSetAttribute(eqlin<32, 7, 32, 256, 1, 18, 3>,    cudaFuncAttributeMaxDynamicSharedMemorySize, SM3);

    // block 0: mul=256, d=1: 1024 m-tiles, full N=256 in one CTA
    eqlin<256, 1, 256, 512, 8, 128, 1><<<148, 512, SM0>>>(x, out, 0, 0, 1024);
    // block 1: mul=128, d=3: 3121 tiles of 42 batches (126 rows)
    eqlin<128, 3, 128, 512, 4, 42, 1><<<148, 512, SM1>>>(x, out, 256, 65536, 3121);
    // block 2: mul=64, d=5: 5243 tiles of 25 batches (125 rows), 3 CTAs/SM
    eqlin<64, 5, 64, 256, 2, 25, 3><<<444, 256, SM2>>>(x, out, 640, 81920, 5243);
    // block 3: mul=32, d=7: 7282 tiles of 18 batches (126 rows), 3 CTAs/SM
    eqlin<32, 7, 32, 256, 1, 18, 3><<<444, 256, SM3>>>(x, out, 960, 86016, 7282);
}

// round 12
// speedup vs baseline: 1.1134x; 1.1134x over previous
#include <cuda_runtime.h>
#include <cuda_fp16.h>
#include <cstdint>

#define FEAT 1184
#define BATCH 131072

// Pre-scaled fp16 weights: fp16(c*W)
__device__ __align__(16) __half g_wh[87040];

__global__ void prep_w(const float* __restrict__ w) {
    int i = blockIdx.x * 256 + threadIdx.x;
    if (i >= 87040) return;
    float c = (i < 65536) ? 0.0625f
            : (i < 81920) ? 0.08838834764831843f
            : (i < 86016) ? 0.125f
            : 0.17677669529663687f;
    g_wh[i] = __float2half_rn(w[i] * c);
}

static __device__ __forceinline__ uint32_t s2u(const void* p) {
    return (uint32_t)__cvta_generic_to_shared(p);
}
static __device__ __forceinline__ uint32_t sw128(uint32_t off) {
    return off ^ ((off >> 3) & 0x70);
}
static __device__ __forceinline__ uint32_t packh2(float a, float b) {
    __half2 h = __floats2half2_rn(a, b);
    return *(uint32_t*)&h;
}
static __device__ __forceinline__ void ldsm4(uint32_t* r, uint32_t addr) {
    asm volatile("ldmatrix.sync.aligned.m8n8.x4.shared.b16 {%0,%1,%2,%3}, [%4];"
                 : "=r"(r[0]), "=r"(r[1]), "=r"(r[2]), "=r"(r[3]) : "r"(addr));
}
static __device__ __forceinline__ void mma16816(float* c, const uint32_t* a,
                                                const uint32_t* b) {
    asm volatile("mma.sync.aligned.m16n8k16.row.col.f32.f16.f16.f32 "
                 "{%0,%1,%2,%3}, {%4,%5,%6,%7}, {%8,%9}, {%0,%1,%2,%3};"
                 : "+f"(c[0]), "+f"(c[1]), "+f"(c[2]), "+f"(c[3])
                 : "r"(a[0]), "r"(a[1]), "r"(a[2]), "r"(a[3]),
                   "r"(b[0]), "r"(b[1]));
}

// y[r, v] = sum_k A[r,k] * fp16(c*W[v,k]),  r = b*D + i,
//   A[r,k] = x[b*FEAT + xo + k*D + i]
// D>1 tiles are batch-aligned: tile m covers batches [m*NBT, m*NBT+NBT),
// rows MROWS = NBT*D <= 128, MMA padded to 128 rows.
template<int MUL, int D, int BN, int NT, int WNW, int NBT, int OCC>
__global__ void __launch_bounds__(NT, OCC) eqlin(
    const float* __restrict__ x, float* __restrict__ out,
    int xo, int wo, int mtiles)
{
    constexpr int KC      = (MUL < 64) ? MUL : 64;
    constexpr int NCH     = MUL / KC;
    constexpr int KSTEPS  = KC / 16;
    constexpr int OCTS    = KC / 8;
    constexpr int WSZ     = NCH * BN * 128;      // resident W bytes
    constexpr int A_OFF   = WSZ;
    constexpr int NABUF   = (D == 1) ? 2 : 1;
    constexpr int STG_OFF = A_OFF + NABUF * 16384;
    constexpr int STRIDE  = KC * D + 4;          // floats; == 4 (mod 32)
    constexpr int F4PB    = KC * D / 4;          // float4 per batch per chunk
    constexpr int STGSZ   = NBT * STRIDE * 4;    // bytes per staging buffer
    constexpr int NSBUF   = (NCH > 1) ? 2 : 1;   // staging depth
    // epilogue staging (D>1): transposed/output layout, two batch passes
    constexpr int BP      = (NBT + 1) / 2;       // batches per pass
    constexpr int BND     = BN * D;              // floats per batch (output)
    constexpr int F4B     = BND / 4;             // float4 per batch (output)
    constexpr int EPI_OFF = STG_OFF + NSBUF * STGSZ;
    constexpr int WARPS   = NT / 32;
    constexpr int WN      = BN / WNW;            // == 32 in all configs
    constexpr int NT8     = WN / 8;
    constexpr int MWARPS  = WARPS / WNW;
    constexpr int MT      = 128 / MWARPS / 16;   // m16 frags per warp
    constexpr int TASKS   = (128 * OCTS) / NT;

    extern __shared__ char smem[];
    const uint32_t sb = s2u(smem);
    const int tid  = threadIdx.x;
    const int lane = tid & 31;
    const int warp = tid >> 5;
    const int wm   = warp / WNW;
    const int wn   = warp % WNW;

    // ---- Resident W (fp16), chunk-major 128B rows, SW128 ----
    for (int e = tid; e < BN * (MUL / 8); e += NT) {
        int v = e / (MUL / 8), o = e % (MUL / 8);
        int k = o * 8;
        uint4 hv = *(const uint4*)(g_wh + wo + (size_t)v * MUL + k);
        uint32_t off = (uint32_t)((k / KC) * (BN * 128) + v * 128 + (k % KC) * 2);
        *(uint4*)(smem + sw128(off)) = hv;
    }

    float acc[MT][NT8][4];
    float st[(D == 1) ? TASKS : 1][8];

    // cp.async: contiguous float4 span of chunk c of tile m into buffer buf
    auto stage_ld = [&](int m, int c, int buf) {
        int B0 = m * NBT;
        for (int e = tid; e < NBT * F4PB; e += NT) {
            int bl = e / F4PB, f = e - bl * F4PB;
            int b = B0 + bl;
            if (b >= BATCH) b = BATCH - 1;
            const float* src = x + (size_t)b * FEAT + xo + c * (KC * D) + f * 4;
            uint32_t dst = sb + STG_OFF + (uint32_t)buf * STGSZ +
                           (uint32_t)(bl * STRIDE + f * 4) * 4;
            asm volatile("cp.async.cg.shared.global [%0], [%1], 16;"
                         :: "r"(dst), "l"(src) : "memory");
        }
        asm volatile("cp.async.commit_group;" ::: "memory");
    };

    // D>1: strided LDS from staging -> fp16 -> swizzled A (rows batch-local)
    auto conv_chunk = [&](int buf) {
        const float* stgF = (const float*)(smem + STG_OFF + buf * STGSZ);
#pragma unroll
        for (int t = 0; t < TASKS; t++) {
            int e = tid + t * NT;
            int rl = e & 127, o = e >> 7;
            int bl = rl / D;
            if (bl > NBT - 1) bl = NBT - 1;        // padding rows
            int i = rl - bl * D;
            const float* s = stgF + bl * STRIDE + (o * 8) * D + i;
            float v[8];
#pragma unroll
            for (int j = 0; j < 8; j++) v[j] = s[j * D];
            uint32_t p0 = packh2(v[0], v[1]), p1 = packh2(v[2], v[3]);
            uint32_t p2 = packh2(v[4], v[5]), p3 = packh2(v[6], v[7]);
            *(uint4*)(smem + A_OFF + sw128((uint32_t)(rl * 128 + o * 16))) =
                make_uint4(p0, p1, p2, p3);
        }
    };

    // D==1: coalesced LDG float4 -> regs -> swizzled A
    auto ldg_chunk = [&](int m, int c) {
#pragma unroll
        for (int t = 0; t < TASKS; t++) {
            int e = tid + t * NT;
            int rl = e & 127, o = e >> 7;
            const float* xp = x + (size_t)(m * 128 + rl) * FEAT + xo + c * KC + o * 8;
            float4 q0 = *(const float4*)xp;
            float4 q1 = *(const float4*)(xp + 4);
            st[t][0] = q0.x; st[t][1] = q0.y; st[t][2] = q0.z; st[t][3] = q0.w;
            st[t][4] = q1.x; st[t][5] = q1.y; st[t][6] = q1.z; st[t][7] = q1.w;
        }
    };
    auto sts_chunk = [&](int buf) {
#pragma unroll
        for (int t = 0; t < TASKS; t++) {
            int e = tid + t * NT;
            int rl = e & 127, o = e >> 7;
            uint32_t p0 = packh2(st[t][0], st[t][1]), p1 = packh2(st[t][2], st[t][3]);
            uint32_t p2 = packh2(st[t][4], st[t][5]), p3 = packh2(st[t][6], st[t][7]);
            *(uint4*)(smem + A_OFF + buf * 16384 +
                      sw128((uint32_t)(rl * 128 + o * 16))) = make_uint4(p0, p1, p2, p3);
        }
    };

    auto mma_chunk = [&](uint32_t aoff, int c) {
        const int q = lane >> 3, p = lane & 7;
#pragma unroll
        for (int s = 0; s < KSTEPS; s++) {
            uint32_t af[MT][4];
#pragma unroll
            for (int mt = 0; mt < MT; mt++) {
                uint32_t row = (uint32_t)(wm * (MT * 16) + mt * 16 + (q & 1) * 8 + p);
                uint32_t kb  = (uint32_t)(s * 32 + (q >> 1) * 16);
                ldsm4(af[mt], sb + aoff + sw128(row * 128 + kb));
            }
#pragma unroll
            for (int ntp = 0; ntp < NT8 / 2; ntp++) {
                uint32_t vv = (uint32_t)(wn * WN + ntp * 16 + (q >> 1) * 8 + p);
                uint32_t kb = (uint32_t)(s * 32 + (q & 1) * 16);
                uint32_t bh[4];
                ldsm4(bh, sb + (uint32_t)(c * (BN * 128)) + sw128(vv * 128 + kb));
#pragma unroll
                for (int t2 = 0; t2 < 2; t2++)
#pragma unroll
                    for (int mt = 0; mt < MT; mt++)
                        mma16816(acc[mt][ntp * 2 + t2], af[mt], bh + 2 * t2);
            }
        }
    };

    auto zero_acc = [&]() {
#pragma unroll
        for (int mt = 0; mt < MT; mt++)
#pragma unroll
            for (int nt = 0; nt < NT8; nt++)
#pragma unroll
                for (int j = 0; j < 4; j++) acc[mt][nt][j] = 0.0f;
    };

    // D>1 epilogue: acc -> smem in OUTPUT layout (scatter on STS side),
    // then linear LDS.128 + coalesced STG.128. Two batch-aligned passes.
    auto epi_d = [&](int m) {
        const int B0 = m * NBT;
        float* epiS = (float*)(smem + EPI_OFF);
        const int rb = wm * (MT * 16) + (lane >> 2);
        const int cb = wn * WN + 2 * (lane & 3);
#pragma unroll 1
        for (int p = 0; p < 2; p++) {
            const int blo = p * BP;
            const int pnb = (NBT - blo < BP) ? (NBT - blo) : BP;
            __syncthreads();       // prior readers of epiS / A done
#pragma unroll
            for (int mt = 0; mt < MT; mt++) {
#pragma unroll
                for (int half = 0; half < 2; half++) {
                    int r  = rb + mt * 16 + half * 8;
                    int bl = r / D;                 // const divisor
                    int i  = r - bl * D;
                    int blp = bl - blo;
                    if (blp >= 0 && blp < pnb) {
                        float* dst = epiS + blp * BND + i;
#pragma unroll
                        for (int nt = 0; nt < NT8; nt++) {
                            int cc = cb + nt * 8;
                            dst[cc * D]       = acc[mt][nt][half * 2];
                            dst[(cc + 1) * D] = acc[mt][nt][half * 2 + 1];
                        }
                    }
                }
            }
            __syncthreads();
            int nf4 = pnb * F4B;
            for (int e = tid; e < nf4; e += NT) {
                int bl = e / F4B;                   // const divisor
                int q  = e - bl * F4B;
                int b  = B0 + blo + bl;
                if (b < BATCH) {
                    float4 val = *(const float4*)(epiS + e * 4);  // linear LDS
                    *(float4*)(out + (size_t)b * FEAT + xo + q * 4) = val;
                }
            }
        }
    };

    if (D == 1) {
        ldg_chunk(blockIdx.x, 0);
        __syncthreads();                       // W visible
        int g = 0;
        for (int m = blockIdx.x; m < mtiles; m += gridDim.x) {
            zero_acc();
#pragma unroll 1
            for (int c = 0; c < NCH; c++) {
                int buf = g & 1;
                sts_chunk(buf);
                __syncthreads();
                int cn = c + 1, mn = m;
                if (cn == NCH) { cn = 0; mn = m + gridDim.x; }
                if (mn < mtiles) ldg_chunk(mn, cn);
                mma_chunk((uint32_t)(A_OFF + buf * 16384), c);
                g++;
            }
            // direct epilogue (contiguous float2 per row)
            const int row_base = m * 128 + wm * (MT * 16) + (lane >> 2);
            const int col_base = wn * WN + 2 * (lane & 3);
#pragma unroll
            for (int mt = 0; mt < MT; mt++)
#pragma unroll
                for (int nt = 0; nt < NT8; nt++) {
                    float* a = acc[mt][nt];
                    int cc = col_base + nt * 8;
                    int r1 = row_base + mt * 16;
                    *(float2*)(out + (size_t)r1 * FEAT + xo + cc) =
                        make_float2(a[0], a[1]);
                    *(float2*)(out + (size_t)(r1 + 8) * FEAT + xo + cc) =
                        make_float2(a[2], a[3]);
                }
        }
    } else if (NCH == 1) {
        // single chunk per tile; single staging buffer, overlap next-tile load
        if (blockIdx.x < mtiles) stage_ld(blockIdx.x, 0, 0);
        for (int m = blockIdx.x; m < mtiles; m += gridDim.x) {
            zero_acc();
            asm volatile("cp.async.wait_group 0;" ::: "memory");
            __syncthreads();                   // staging + W visible; A free
            conv_chunk(0);
            __syncthreads();                   // A ready; staging reusable
            int mn = m + gridDim.x;
            if (mn < mtiles) stage_ld(mn, 0, 0);   // overlaps MMA + epilogue
            mma_chunk((uint32_t)A_OFF, 0);
            epi_d(m);
        }
    } else {
        // NCH==2 (block1): depth-2 staging pipeline across chunks
        int ms = blockIdx.x, cs = 0;
        auto stage_adv = [&](int buf) {
            if (ms < mtiles) stage_ld(ms, cs, buf);
            else asm volatile("cp.async.commit_group;" ::: "memory");
            if (++cs == NCH) { cs = 0; ms += gridDim.x; }
        };
        stage_adv(0);
        stage_adv(1);
        int g = 0;
        for (int m = blockIdx.x; m < mtiles; m += gridDim.x) {
            zero_acc();
#pragma unroll 1
            for (int c = 0; c < NCH; c++) {
                asm volatile("cp.async.wait_group 1;" ::: "memory");
                __syncthreads();               // staging g visible; A free
                conv_chunk(g & 1);
                __syncthreads();               // A ready; staging buf reusable
                stage_adv(g & 1);              // chunk g+2 into same buf
                mma_chunk((uint32_t)A_OFF, c);
                g++;
            }
            epi_d(m);
        }
    }
}

extern "C" void kernel_launch(void* const* d_in, const int* in_sizes, int n_in,
                              void* d_out, int out_size)
{
    const float* x = (const float*)d_in[0];
    const float* w = (const float*)d_in[1];
    float* out = (float*)d_out;

    prep_w<<<(87040 + 255) / 256, 256>>>(w);

    // smem budgets (mirror template math):
    //   WSZ + NABUF*16384 + NSBUF*STGSZ + BP*BN*D*4
    constexpr int SM0 = 4 * 256 * 128 + 2 * 16384;                          // 163840
    constexpr int SM1 = 32768 + 16384 + 2 * (42 * 196 * 4) + 21 * 384 * 4; // 147264
    constexpr int SM2 = 8192 + 16384 + (25 * 324 * 4) + 13 * 320 * 4;      // 73616
    constexpr int SM3 = 4096 + 16384 + (18 * 228 * 4) + 9 * 224 * 4;       // 44960

    cudaFuncSetAttribute(eqlin<256, 1, 256, 512, 8, 128, 1>, cudaFuncAttributeMaxDynamicSharedMemorySize, SM0);
    cudaFuncSetAttribute(eqlin<128, 3, 128, 512, 4, 42, 1>,  cudaFuncAttributeMaxDynamicSharedMemorySize, SM1);
    cudaFuncSetAttribute(eqlin<64, 5, 64, 256, 2, 25, 3>,    cudaFuncAttributeMaxDynamicSharedMemorySize, SM2);
    cudaFuncSetAttribute(eqlin<32, 7, 32, 256, 1, 18, 3>,    cudaFuncAttributeMaxDynamicSharedMemorySize, SM3);

    // block 0: mul=256, d=1: 1024 m-tiles, full N=256 in one CTA
    eqlin<256, 1, 256, 512, 8, 128, 1><<<148, 512, SM0>>>(x, out, 0, 0, 1024);
    // block 1: mul=128, d=3: 3121 tiles of 42 batches (126 rows)
    eqlin<128, 3, 128, 512, 4, 42, 1><<<148, 512, SM1>>>(x, out, 256, 65536, 3121);
    // block 2: mul=64, d=5: 5243 tiles of 25 batches (125 rows), 3 CTAs/SM
    eqlin<64, 5, 64, 256, 2, 25, 3><<<444, 256, SM2>>>(x, out, 640, 81920, 5243);
    // block 3: mul=32, d=7: 7282 tiles of 18 batches (126 rows), 3 CTAs/SM
    eqlin<32, 7, 32, 256, 1, 18, 3><<<444, 256, SM3>>>(x, out, 960, 86016, 7282);
}

// round 13
// speedup vs baseline: 1.1604x; 1.0422x over previous
#include <cuda_runtime.h>
#include <cuda_fp16.h>
#include <cstdint>

#define FEAT 1184
#define BATCH 131072

// Pre-scaled fp16 weights: fp16(c*W)
__device__ __align__(16) __half g_wh[87040];

__global__ void prep_w(const float* __restrict__ w) {
    int i = blockIdx.x * 256 + threadIdx.x;
    if (i >= 87040) return;
    float c = (i < 65536) ? 0.0625f
            : (i < 81920) ? 0.08838834764831843f
            : (i < 86016) ? 0.125f
            : 0.17677669529663687f;
    g_wh[i] = __float2half_rn(w[i] * c);
}

static __device__ __forceinline__ uint32_t s2u(const void* p) {
    return (uint32_t)__cvta_generic_to_shared(p);
}
static __device__ __forceinline__ uint32_t sw128(uint32_t off) {
    return off ^ ((off >> 3) & 0x70);
}
static __device__ __forceinline__ uint32_t packh2(float a, float b) {
    __half2 h = __floats2half2_rn(a, b);
    return *(uint32_t*)&h;
}
static __device__ __forceinline__ void ldsm4(uint32_t* r, uint32_t addr) {
    asm volatile("ldmatrix.sync.aligned.m8n8.x4.shared.b16 {%0,%1,%2,%3}, [%4];"
                 : "=r"(r[0]), "=r"(r[1]), "=r"(r[2]), "=r"(r[3]) : "r"(addr));
}
static __device__ __forceinline__ void mma16816(float* c, const uint32_t* a,
                                                const uint32_t* b) {
    asm volatile("mma.sync.aligned.m16n8k16.row.col.f32.f16.f16.f32 "
                 "{%0,%1,%2,%3}, {%4,%5,%6,%7}, {%8,%9}, {%0,%1,%2,%3};"
                 : "+f"(c[0]), "+f"(c[1]), "+f"(c[2]), "+f"(c[3])
                 : "r"(a[0]), "r"(a[1]), "r"(a[2]), "r"(a[3]),
                   "r"(b[0]), "r"(b[1]));
}

// y[r, v] = sum_k A[r,k] * fp16(c*W[v,k]),  r = b*D + i,
//   A[r,k] = x[b*FEAT + xo + k*D + i]
// D>1 tiles are batch-aligned: tile m covers batches [m*NBT, m*NBT+NBT),
// rows MROWS = NBT*D <= 128, MMA padded to 128 rows.
template<int MUL, int D, int BN, int NT, int WNW, int NBT, int OCC>
__global__ void __launch_bounds__(NT, OCC) eqlin(
    const float* __restrict__ x, float* __restrict__ out,
    int xo, int wo, int mtiles)
{
    constexpr int KC      = (MUL < 64) ? MUL : 64;
    constexpr int NCH     = MUL / KC;
    constexpr int KSTEPS  = KC / 16;
    constexpr int OCTS    = KC / 8;
    constexpr int WSZ     = NCH * BN * 128;      // resident W bytes
    constexpr int A_OFF   = WSZ;
    constexpr int NABUF   = (D == 1) ? 2 : 1;
    constexpr int STG_OFF = A_OFF + NABUF * 16384;
    constexpr int STRIDE  = KC * D + 4;          // floats; == 4 (mod 32)
    constexpr int F4PB    = KC * D / 4;          // float4 per batch per chunk
    constexpr int STGSZ   = NBT * STRIDE * 4;    // bytes per staging buffer
    constexpr int NSBUF   = (NCH > 1) ? 2 : 1;   // staging depth
    // epilogue staging (D>1): transposed/output layout, two batch passes
    constexpr int BP      = (NBT + 1) / 2;       // batches per pass
    constexpr int BND     = BN * D;              // floats per batch (output)
    constexpr int F4B     = BND / 4;             // float4 per batch (output)
    constexpr int EPI_OFF = STG_OFF + NSBUF * STGSZ;
    constexpr int WARPS   = NT / 32;
    constexpr int WN      = BN / WNW;            // == 32 in all configs
    constexpr int NT8     = WN / 8;
    constexpr int MWARPS  = WARPS / WNW;
    constexpr int MT      = 128 / MWARPS / 16;   // m16 frags per warp
    constexpr int TASKS   = (128 * OCTS) / NT;

    extern __shared__ char smem[];
    const uint32_t sb = s2u(smem);
    const int tid  = threadIdx.x;
    const int lane = tid & 31;
    const int warp = tid >> 5;
    const int wm   = warp / WNW;
    const int wn   = warp % WNW;

    // ---- Resident W (fp16), chunk-major 128B rows, SW128 ----
    for (int e = tid; e < BN * (MUL / 8); e += NT) {
        int v = e / (MUL / 8), o = e % (MUL / 8);
        int k = o * 8;
        uint4 hv = *(const uint4*)(g_wh + wo + (size_t)v * MUL + k);
        uint32_t off = (uint32_t)((k / KC) * (BN * 128) + v * 128 + (k % KC) * 2);
        *(uint4*)(smem + sw128(off)) = hv;
    }

    float acc[MT][NT8][4];
    float st[(D == 1) ? TASKS : 1][8];

    // cp.async: contiguous float4 span of chunk c of tile m into buffer buf
    auto stage_ld = [&](int m, int c, int buf) {
        int B0 = m * NBT;
        for (int e = tid; e < NBT * F4PB; e += NT) {
            int bl = e / F4PB, f = e - bl * F4PB;
            int b = B0 + bl;
            if (b >= BATCH) b = BATCH - 1;
            const float* src = x + (size_t)b * FEAT + xo + c * (KC * D) + f * 4;
            uint32_t dst = sb + STG_OFF + (uint32_t)buf * STGSZ +
                           (uint32_t)(bl * STRIDE + f * 4) * 4;
            asm volatile("cp.async.cg.shared.global [%0], [%1], 16;"
                         :: "r"(dst), "l"(src) : "memory");
        }
        asm volatile("cp.async.commit_group;" ::: "memory");
    };

    // D>1: strided LDS from staging -> fp16 -> swizzled A (rows batch-local)
    auto conv_chunk = [&](int buf) {
        const float* stgF = (const float*)(smem + STG_OFF + buf * STGSZ);
#pragma unroll
        for (int t = 0; t < TASKS; t++) {
            int e = tid + t * NT;
            int rl = e & 127, o = e >> 7;
            int bl = rl / D;
            if (bl > NBT - 1) bl = NBT - 1;        // padding rows
            int i = rl - bl * D;
            const float* s = stgF + bl * STRIDE + (o * 8) * D + i;
            float v[8];
#pragma unroll
            for (int j = 0; j < 8; j++) v[j] = s[j * D];
            uint32_t p0 = packh2(v[0], v[1]), p1 = packh2(v[2], v[3]);
            uint32_t p2 = packh2(v[4], v[5]), p3 = packh2(v[6], v[7]);
            *(uint4*)(smem + A_OFF + sw128((uint32_t)(rl * 128 + o * 16))) =
                make_uint4(p0, p1, p2, p3);
        }
    };

    // D==1: coalesced LDG float4 -> regs -> swizzled A
    auto ldg_chunk = [&](int m, int c) {
#pragma unroll
        for (int t = 0; t < TASKS; t++) {
            int e = tid + t * NT;
            int rl = e & 127, o = e >> 7;
            const float* xp = x + (size_t)(m * 128 + rl) * FEAT + xo + c * KC + o * 8;
            float4 q0 = *(const float4*)xp;
            float4 q1 = *(const float4*)(xp + 4);
            st[t][0] = q0.x; st[t][1] = q0.y; st[t][2] = q0.z; st[t][3] = q0.w;
            st[t][4] = q1.x; st[t][5] = q1.y; st[t][6] = q1.z; st[t][7] = q1.w;
        }
    };
    auto sts_chunk = [&](int buf) {
#pragma unroll
        for (int t = 0; t < TASKS; t++) {
            int e = tid + t * NT;
            int rl = e & 127, o = e >> 7;
            uint32_t p0 = packh2(st[t][0], st[t][1]), p1 = packh2(st[t][2], st[t][3]);
            uint32_t p2 = packh2(st[t][4], st[t][5]), p3 = packh2(st[t][6], st[t][7]);
            *(uint4*)(smem + A_OFF + buf * 16384 +
                      sw128((uint32_t)(rl * 128 + o * 16))) = make_uint4(p0, p1, p2, p3);
        }
    };

    auto mma_chunk = [&](uint32_t aoff, int c) {
        const int q = lane >> 3, p = lane & 7;
#pragma unroll
        for (int s = 0; s < KSTEPS; s++) {
            uint32_t af[MT][4];
#pragma unroll
            for (int mt = 0; mt < MT; mt++) {
                uint32_t row = (uint32_t)(wm * (MT * 16) + mt * 16 + (q & 1) * 8 + p);
                uint32_t kb  = (uint32_t)(s * 32 + (q >> 1) * 16);
                ldsm4(af[mt], sb + aoff + sw128(row * 128 + kb));
            }
#pragma unroll
            for (int ntp = 0; ntp < NT8 / 2; ntp++) {
                uint32_t vv = (uint32_t)(wn * WN + ntp * 16 + (q >> 1) * 8 + p);
                uint32_t kb = (uint32_t)(s * 32 + (q & 1) * 16);
                uint32_t bh[4];
                ldsm4(bh, sb + (uint32_t)(c * (BN * 128)) + sw128(vv * 128 + kb));
#pragma unroll
                for (int t2 = 0; t2 < 2; t2++)
#pragma unroll
                    for (int mt = 0; mt < MT; mt++)
                        mma16816(acc[mt][ntp * 2 + t2], af[mt], bh + 2 * t2);
            }
        }
    };

    auto zero_acc = [&]() {
#pragma unroll
        for (int mt = 0; mt < MT; mt++)
#pragma unroll
            for (int nt = 0; nt < NT8; nt++)
#pragma unroll
                for (int j = 0; j < 4; j++) acc[mt][nt][j] = 0.0f;
    };

    // D>1 epilogue: acc -> smem in OUTPUT layout (scatter on STS side),
    // then linear LDS.128 + coalesced STG.128. Two batch-aligned passes.
    auto epi_d = [&](int m) {
        const int B0 = m * NBT;
        float* epiS = (float*)(smem + EPI_OFF);
        const int rb = wm * (MT * 16) + (lane >> 2);
        const int cb = wn * WN + 2 * (lane & 3);
#pragma unroll 1
        for (int p = 0; p < 2; p++) {
            const int blo = p * BP;
            const int pnb = (NBT - blo < BP) ? (NBT - blo) : BP;
            __syncthreads();       // prior readers of epiS / A done
#pragma unroll
            for (int mt = 0; mt < MT; mt++) {
#pragma unroll
                for (int half = 0; half < 2; half++) {
                    int r  = rb + mt * 16 + half * 8;
                    int bl = r / D;                 // const divisor
                    int i  = r - bl * D;
                    int blp = bl - blo;
                    if (blp >= 0 && blp < pnb) {
                        float* dst = epiS + blp * BND + i;
#pragma unroll
                        for (int nt = 0; nt < NT8; nt++) {
                            int cc = cb + nt * 8;
                            dst[cc * D]       = acc[mt][nt][half * 2];
                            dst[(cc + 1) * D] = acc[mt][nt][half * 2 + 1];
                        }
                    }
                }
            }
            __syncthreads();
            int nf4 = pnb * F4B;
            for (int e = tid; e < nf4; e += NT) {
                int bl = e / F4B;                   // const divisor
                int q  = e - bl * F4B;
                int b  = B0 + blo + bl;
                if (b < BATCH) {
                    float4 val = *(const float4*)(epiS + e * 4);  // linear LDS
                    *(float4*)(out + (size_t)b * FEAT + xo + q * 4) = val;
                }
            }
        }
    };

    if (D == 1) {
        ldg_chunk(blockIdx.x, 0);
        __syncthreads();                       // W visible
        int g = 0;
        for (int m = blockIdx.x; m < mtiles; m += gridDim.x) {
            zero_acc();
#pragma unroll 1
            for (int c = 0; c < NCH; c++) {
                int buf = g & 1;
                sts_chunk(buf);
                __syncthreads();
                int cn = c + 1, mn = m;
                if (cn == NCH) { cn = 0; mn = m + gridDim.x; }
                if (mn < mtiles) ldg_chunk(mn, cn);
                mma_chunk((uint32_t)(A_OFF + buf * 16384), c);
                g++;
            }
            // direct epilogue (contiguous float2 per row)
            const int row_base = m * 128 + wm * (MT * 16) + (lane >> 2);
            const int col_base = wn * WN + 2 * (lane & 3);
#pragma unroll
            for (int mt = 0; mt < MT; mt++)
#pragma unroll
                for (int nt = 0; nt < NT8; nt++) {
                    float* a = acc[mt][nt];
                    int cc = col_base + nt * 8;
                    int r1 = row_base + mt * 16;
                    *(float2*)(out + (size_t)r1 * FEAT + xo + cc) =
                        make_float2(a[0], a[1]);
                    *(float2*)(out + (size_t)(r1 + 8) * FEAT + xo + cc) =
                        make_float2(a[2], a[3]);
                }
        }
    } else if (NCH == 1) {
        // single chunk per tile; single staging buffer, overlap next-tile load
        if (blockIdx.x < mtiles) stage_ld(blockIdx.x, 0, 0);
        for (int m = blockIdx.x; m < mtiles; m += gridDim.x) {
            zero_acc();
            asm volatile("cp.async.wait_group 0;" ::: "memory");
            __syncthreads();                   // staging + W visible; A free
            conv_chunk(0);
            __syncthreads();                   // A ready; staging reusable
            int mn = m + gridDim.x;
            if (mn < mtiles) stage_ld(mn, 0, 0);   // overlaps MMA + epilogue
            mma_chunk((uint32_t)A_OFF, 0);
            epi_d(m);
        }
    } else {
        // NCH==2 (block1): depth-2 staging pipeline across chunks
        int ms = blockIdx.x, cs = 0;
        auto stage_adv = [&](int buf) {
            if (ms < mtiles) stage_ld(ms, cs, buf);
            else asm volatile("cp.async.commit_group;" ::: "memory");
            if (++cs == NCH) { cs = 0; ms += gridDim.x; }
        };
        stage_adv(0);
        stage_adv(1);
        int g = 0;
        for (int m = blockIdx.x; m < mtiles; m += gridDim.x) {
            zero_acc();
#pragma unroll 1
            for (int c = 0; c < NCH; c++) {
                asm volatile("cp.async.wait_group 1;" ::: "memory");
                __syncthreads();               // staging g visible; A free
                conv_chunk(g & 1);
                __syncthreads();               // A ready; staging buf reusable
                stage_adv(g & 1);              // chunk g+2 into same buf
                mma_chunk((uint32_t)A_OFF, c);
                g++;
            }
            epi_d(m);
        }
    }
}

extern "C" void kernel_launch(void* const* d_in, const int* in_sizes, int n_in,
                              void* d_out, int out_size)
{
    const float* x = (const float*)d_in[0];
    const float* w = (const float*)d_in[1];
    float* out = (float*)d_out;

    // Lazily-created side stream + fork/join events (kernel_launch runs only a
    // few times: correctness + capture; work is identical & deterministic).
    static cudaStream_t sB = nullptr;
    static cudaEvent_t evFork = nullptr, evJoin = nullptr;
    if (sB == nullptr) {
        cudaStreamCreateWithFlags(&sB, cudaStreamNonBlocking);
        cudaEventCreateWithFlags(&evFork, cudaEventDisableTiming);
        cudaEventCreateWithFlags(&evJoin, cudaEventDisableTiming);
    }

    // smem budgets (mirror template math):
    //   WSZ + NABUF*16384 + NSBUF*STGSZ + BP*BN*D*4
    constexpr int SM0 = 4 * 256 * 128 + 2 * 16384;                          // 163840
    constexpr int SM1 = 32768 + 16384 + 2 * (42 * 196 * 4) + 21 * 384 * 4; // 147264
    constexpr int SM2 = 8192 + 16384 + (25 * 324 * 4) + 13 * 320 * 4;      // 73616
    constexpr int SM3 = 4096 + 16384 + (18 * 228 * 4) + 9 * 224 * 4;       // 44960

    cudaFuncSetAttribute(eqlin<256, 1, 256, 512, 8, 128, 1>, cudaFuncAttributeMaxDynamicSharedMemorySize, SM0);
    cudaFuncSetAttribute(eqlin<128, 3, 128, 512, 4, 42, 1>,  cudaFuncAttributeMaxDynamicSharedMemorySize, SM1);
    cudaFuncSetAttribute(eqlin<64, 5, 64, 256, 2, 25, 3>,    cudaFuncAttributeMaxDynamicSharedMemorySize, SM2);
    cudaFuncSetAttribute(eqlin<32, 7, 32, 256, 1, 18, 3>,    cudaFuncAttributeMaxDynamicSharedMemorySize, SM3);

    // prep on the main stream; both streams depend on it
    prep_w<<<(87040 + 255) / 256, 256>>>(w);
    cudaEventRecord(evFork, 0);
    cudaStreamWaitEvent(sB, evFork, 0);

    // stream B: block1 (mul=128, d=3) then block2 (mul=64, d=5)
    eqlin<128, 3, 128, 512, 4, 42, 1><<<148, 512, SM1, sB>>>(x, out, 256, 65536, 3121);
    eqlin<64, 5, 64, 256, 2, 25, 3><<<444, 256, SM2, sB>>>(x, out, 640, 81920, 5243);

    // main stream: block0 (mul=256, d=1) then block3 (mul=32, d=7)
    eqlin<256, 1, 256, 512, 8, 128, 1><<<148, 512, SM0>>>(x, out, 0, 0, 1024);
    eqlin<32, 7, 32, 256, 1, 18, 3><<<444, 256, SM3>>>(x, out, 960, 86016, 7282);

    // join
    cudaEventRecord(evJoin, sB);
    cudaStreamWaitEvent(0, evJoin, 0);
}

// round 14
// speedup vs baseline: 1.2280x; 1.0583x over previous
#include <cuda_runtime.h>
#include <cuda_fp16.h>
#include <cstdint>

#define FEAT 1184
#define BATCH 131072

// Pre-scaled fp16 weights: fp16(c*W)
__device__ __align__(16) __half g_wh[87040];

__global__ void prep_w(const float* __restrict__ w) {
    int i = blockIdx.x * 256 + threadIdx.x;
    if (i >= 87040) return;
    float c = (i < 65536) ? 0.0625f
            : (i < 81920) ? 0.08838834764831843f
            : (i < 86016) ? 0.125f
            : 0.17677669529663687f;
    g_wh[i] = __float2half_rn(w[i] * c);
}

static __device__ __forceinline__ uint32_t s2u(const void* p) {
    return (uint32_t)__cvta_generic_to_shared(p);
}
static __device__ __forceinline__ uint32_t sw128(uint32_t off) {
    return off ^ ((off >> 3) & 0x70);
}
static __device__ __forceinline__ uint32_t packh2(float a, float b) {
    __half2 h = __floats2half2_rn(a, b);
    return *(uint32_t*)&h;
}
static __device__ __forceinline__ void ldsm4(uint32_t* r, uint32_t addr) {
    asm volatile("ldmatrix.sync.aligned.m8n8.x4.shared.b16 {%0,%1,%2,%3}, [%4];"
                 : "=r"(r[0]), "=r"(r[1]), "=r"(r[2]), "=r"(r[3]) : "r"(addr));
}
static __device__ __forceinline__ void mma16816(float* c, const uint32_t* a,
                                                const uint32_t* b) {
    asm volatile("mma.sync.aligned.m16n8k16.row.col.f32.f16.f16.f32 "
                 "{%0,%1,%2,%3}, {%4,%5,%6,%7}, {%8,%9}, {%0,%1,%2,%3};"
                 : "+f"(c[0]), "+f"(c[1]), "+f"(c[2]), "+f"(c[3])
                 : "r"(a[0]), "r"(a[1]), "r"(a[2]), "r"(a[3]),
                   "r"(b[0]), "r"(b[1]));
}

// y[r, v] = sum_k A[r,k] * fp16(c*W[v,k]),  r = b*D + i,
//   A[r,k] = x[b*FEAT + xo + k*D + i]
// Tiles are batch-aligned: tile m covers batches [m*NBT, m*NBT+NBT),
// rows MROWS = NBT*D <= 128, MMA padded to 128 rows. (D==1: NBT=128 exact.)
template<int MUL, int D, int BN, int NT, int WNW, int NBT, int OCC>
__global__ void __launch_bounds__(NT, OCC) eqlin(
    const float* __restrict__ x, float* __restrict__ out,
    int xo, int wo, int mtiles)
{
    constexpr int KC      = (MUL < 64) ? MUL : 64;
    constexpr int NCH     = MUL / KC;
    constexpr int KSTEPS  = KC / 16;
    constexpr int OCTS    = KC / 8;
    constexpr int WSZ     = NCH * BN * 128;      // resident W bytes
    constexpr int A_OFF   = WSZ;                 // single A buffer (16 KB)
    constexpr int STG_OFF = A_OFF + 16384;
    constexpr int STRIDE  = KC * D + 4;          // floats; == 4 (mod 32)
    constexpr int F4PB    = KC * D / 4;          // float4 per batch per chunk
    constexpr int STGSZ   = NBT * STRIDE * 4;    // bytes per staging buffer
    constexpr int NSBUF   = (NCH > 1) ? 2 : 1;   // staging depth
    // epilogue staging (D>1): transposed/output layout, two batch passes
    constexpr int BP      = (NBT + 1) / 2;       // batches per pass
    constexpr int BND     = BN * D;              // floats per batch (output)
    constexpr int F4B     = BND / 4;             // float4 per batch (output)
    constexpr int EPI_OFF = STG_OFF + NSBUF * STGSZ;
    constexpr int WARPS   = NT / 32;
    constexpr int WN      = BN / WNW;            // == 32 in all configs
    constexpr int NT8     = WN / 8;
    constexpr int MWARPS  = WARPS / WNW;
    constexpr int MT      = 128 / MWARPS / 16;   // m16 frags per warp
    constexpr int TASKS   = (128 * OCTS) / NT;

    extern __shared__ char smem[];
    const uint32_t sb = s2u(smem);
    const int tid  = threadIdx.x;
    const int lane = tid & 31;
    const int warp = tid >> 5;
    const int wm   = warp / WNW;
    const int wn   = warp % WNW;

    // ---- Resident W (fp16), chunk-major 128B rows, SW128 ----
    for (int e = tid; e < BN * (MUL / 8); e += NT) {
        int v = e / (MUL / 8), o = e % (MUL / 8);
        int k = o * 8;
        uint4 hv = *(const uint4*)(g_wh + wo + (size_t)v * MUL + k);
        uint32_t off = (uint32_t)((k / KC) * (BN * 128) + v * 128 + (k % KC) * 2);
        *(uint4*)(smem + sw128(off)) = hv;
    }

    float acc[MT][NT8][4];

    // cp.async: contiguous float4 span of chunk c of tile m into buffer buf
    auto stage_ld = [&](int m, int c, int buf) {
        int B0 = m * NBT;
        for (int e = tid; e < NBT * F4PB; e += NT) {
            int bl = e / F4PB, f = e - bl * F4PB;
            int b = B0 + bl;
            if (b >= BATCH) b = BATCH - 1;
            const float* src = x + (size_t)b * FEAT + xo + c * (KC * D) + f * 4;
            uint32_t dst = sb + STG_OFF + (uint32_t)buf * STGSZ +
                           (uint32_t)(bl * STRIDE + f * 4) * 4;
            asm volatile("cp.async.cg.shared.global [%0], [%1], 16;"
                         :: "r"(dst), "l"(src) : "memory");
        }
        asm volatile("cp.async.commit_group;" ::: "memory");
    };

    // strided LDS from staging -> fp16 -> swizzled A (rows batch-local)
    // D==1 degenerates to linear LDS.128 reads.
    auto conv_chunk = [&](int buf) {
        const float* stgF = (const float*)(smem + STG_OFF + buf * STGSZ);
#pragma unroll
        for (int t = 0; t < TASKS; t++) {
            int e = tid + t * NT;
            int rl = e & 127, o = e >> 7;
            int bl = rl / D;
            if (bl > NBT - 1) bl = NBT - 1;        // padding rows
            int i = rl - bl * D;
            const float* s = stgF + bl * STRIDE + (o * 8) * D + i;
            float v[8];
#pragma unroll
            for (int j = 0; j < 8; j++) v[j] = s[j * D];
            uint32_t p0 = packh2(v[0], v[1]), p1 = packh2(v[2], v[3]);
            uint32_t p2 = packh2(v[4], v[5]), p3 = packh2(v[6], v[7]);
            *(uint4*)(smem + A_OFF + sw128((uint32_t)(rl * 128 + o * 16))) =
                make_uint4(p0, p1, p2, p3);
        }
    };

    auto mma_chunk = [&](int c) {
        const int q = lane >> 3, p = lane & 7;
#pragma unroll
        for (int s = 0; s < KSTEPS; s++) {
            uint32_t af[MT][4];
#pragma unroll
            for (int mt = 0; mt < MT; mt++) {
                uint32_t row = (uint32_t)(wm * (MT * 16) + mt * 16 + (q & 1) * 8 + p);
                uint32_t kb  = (uint32_t)(s * 32 + (q >> 1) * 16);
                ldsm4(af[mt], sb + (uint32_t)A_OFF + sw128(row * 128 + kb));
            }
#pragma unroll
            for (int ntp = 0; ntp < NT8 / 2; ntp++) {
                uint32_t vv = (uint32_t)(wn * WN + ntp * 16 + (q >> 1) * 8 + p);
                uint32_t kb = (uint32_t)(s * 32 + (q & 1) * 16);
                uint32_t bh[4];
                ldsm4(bh, sb + (uint32_t)(c * (BN * 128)) + sw128(vv * 128 + kb));
#pragma unroll
                for (int t2 = 0; t2 < 2; t2++)
#pragma unroll
                    for (int mt = 0; mt < MT; mt++)
                        mma16816(acc[mt][ntp * 2 + t2], af[mt], bh + 2 * t2);
            }
        }
    };

    auto zero_acc = [&]() {
#pragma unroll
        for (int mt = 0; mt < MT; mt++)
#pragma unroll
            for (int nt = 0; nt < NT8; nt++)
#pragma unroll
                for (int j = 0; j < 4; j++) acc[mt][nt][j] = 0.0f;
    };

    // D==1 epilogue: direct contiguous float2 stores
    auto epi_1 = [&](int m) {
        const int row_base = m * 128 + wm * (MT * 16) + (lane >> 2);
        const int col_base = wn * WN + 2 * (lane & 3);
#pragma unroll
        for (int mt = 0; mt < MT; mt++)
#pragma unroll
            for (int nt = 0; nt < NT8; nt++) {
                float* a = acc[mt][nt];
                int cc = col_base + nt * 8;
                int r1 = row_base + mt * 16;
                *(float2*)(out + (size_t)r1 * FEAT + xo + cc) =
                    make_float2(a[0], a[1]);
                *(float2*)(out + (size_t)(r1 + 8) * FEAT + xo + cc) =
                    make_float2(a[2], a[3]);
            }
    };

    // D>1 epilogue: acc -> smem in OUTPUT layout (scatter on STS side),
    // then linear LDS.128 + coalesced STG.128. Two batch-aligned passes.
    auto epi_d = [&](int m) {
        const int B0 = m * NBT;
        float* epiS = (float*)(smem + EPI_OFF);
        const int rb = wm * (MT * 16) + (lane >> 2);
        const int cb = wn * WN + 2 * (lane & 3);
#pragma unroll 1
        for (int p = 0; p < 2; p++) {
            const int blo = p * BP;
            const int pnb = (NBT - blo < BP) ? (NBT - blo) : BP;
            __syncthreads();       // prior readers of epiS / A done
#pragma unroll
            for (int mt = 0; mt < MT; mt++) {
#pragma unroll
                for (int half = 0; half < 2; half++) {
                    int r  = rb + mt * 16 + half * 8;
                    int bl = r / D;                 // const divisor
                    int i  = r - bl * D;
                    int blp = bl - blo;
                    if (blp >= 0 && blp < pnb) {
                        float* dst = epiS + blp * BND + i;
#pragma unroll
                        for (int nt = 0; nt < NT8; nt++) {
                            int cc = cb + nt * 8;
                            dst[cc * D]       = acc[mt][nt][half * 2];
                            dst[(cc + 1) * D] = acc[mt][nt][half * 2 + 1];
                        }
                    }
                }
            }
            __syncthreads();
            int nf4 = pnb * F4B;
            for (int e = tid; e < nf4; e += NT) {
                int bl = e / F4B;                   // const divisor
                int q  = e - bl * F4B;
                int b  = B0 + blo + bl;
                if (b < BATCH) {
                    float4 val = *(const float4*)(epiS + e * 4);  // linear LDS
                    *(float4*)(out + (size_t)b * FEAT + xo + q * 4) = val;
                }
            }
        }
    };

    if (NCH == 1) {
        // single chunk per tile; single staging buffer, overlap next-tile load
        if (blockIdx.x < mtiles) stage_ld(blockIdx.x, 0, 0);
        for (int m = blockIdx.x; m < mtiles; m += gridDim.x) {
            zero_acc();
            asm volatile("cp.async.wait_group 0;" ::: "memory");
            __syncthreads();                   // staging + W visible; A free
            conv_chunk(0);
            __syncthreads();                   // A ready; staging reusable
            int mn = m + gridDim.x;
            if (mn < mtiles) stage_ld(mn, 0, 0);   // overlaps MMA + epilogue
            mma_chunk(0);
            epi_d(m);
        }
    } else {
        // NCH>=2: depth-2 staging pipeline across chunks
        int ms = blockIdx.x, cs = 0;
        auto stage_adv = [&](int buf) {
            if (ms < mtiles) stage_ld(ms, cs, buf);
            else asm volatile("cp.async.commit_group;" ::: "memory");
            if (++cs == NCH) { cs = 0; ms += gridDim.x; }
        };
        stage_adv(0);
        stage_adv(1);
        int g = 0;
        for (int m = blockIdx.x; m < mtiles; m += gridDim.x) {
            zero_acc();
#pragma unroll 1
            for (int c = 0; c < NCH; c++) {
                asm volatile("cp.async.wait_group 1;" ::: "memory");
                __syncthreads();               // staging g visible; A free
                conv_chunk(g & 1);
                __syncthreads();               // A ready; staging buf reusable
                stage_adv(g & 1);              // chunk g+2 into same buf
                mma_chunk(c);
                g++;
            }
            if (D == 1) epi_1(m); else epi_d(m);
        }
    }
}

extern "C" void kernel_launch(void* const* d_in, const int* in_sizes, int n_in,
                              void* d_out, int out_size)
{
    const float* x = (const float*)d_in[0];
    const float* w = (const float*)d_in[1];
    float* out = (float*)d_out;

    // Lazily-created side stream + fork/join events (kernel_launch runs only a
    // few times: correctness + capture; work is identical & deterministic).
    static cudaStream_t sB = nullptr;
    static cudaEvent_t evFork = nullptr, evJoin = nullptr;
    if (sB == nullptr) {
        cudaStreamCreateWithFlags(&sB, cudaStreamNonBlocking);
        cudaEventCreateWithFlags(&evFork, cudaEventDisableTiming);
        cudaEventCreateWithFlags(&evJoin, cudaEventDisableTiming);
    }

    // smem budgets (mirror template math):
    //   WSZ + 16384 + NSBUF*STGSZ (+ BP*BN*D*4 when D>1)
    constexpr int SM0 = 131072 + 16384 + 2 * (128 * 68 * 4);               // 217088
    constexpr int SM1 = 32768 + 16384 + 2 * (42 * 196 * 4) + 21 * 384 * 4; // 147264
    constexpr int SM2 = 8192 + 16384 + (25 * 324 * 4) + 13 * 320 * 4;      // 73616
    constexpr int SM3 = 4096 + 16384 + (18 * 228 * 4) + 9 * 224 * 4;       // 44960

    cudaFuncSetAttribute(eqlin<256, 1, 256, 512, 8, 128, 1>, cudaFuncAttributeMaxDynamicSharedMemorySize, SM0);
    cudaFuncSetAttribute(eqlin<128, 3, 128, 512, 4, 42, 1>,  cudaFuncAttributeMaxDynamicSharedMemorySize, SM1);
    cudaFuncSetAttribute(eqlin<64, 5, 64, 256, 2, 25, 3>,    cudaFuncAttributeMaxDynamicSharedMemorySize, SM2);
    cudaFuncSetAttribute(eqlin<32, 7, 32, 256, 1, 18, 3>,    cudaFuncAttributeMaxDynamicSharedMemorySize, SM3);

    // prep on the main stream; both streams depend on it
    prep_w<<<(87040 + 255) / 256, 256>>>(w);
    cudaEventRecord(evFork, 0);
    cudaStreamWaitEvent(sB, evFork, 0);

    // stream B: block1 (mul=128, d=3) then block2 (mul=64, d=5)
    eqlin<128, 3, 128, 512, 4, 42, 1><<<148, 512, SM1, sB>>>(x, out, 256, 65536, 3121);
    eqlin<64, 5, 64, 256, 2, 25, 3><<<444, 256, SM2, sB>>>(x, out, 640, 81920, 5243);

    // main stream: block0 (mul=256, d=1) then block3 (mul=32, d=7)
    eqlin<256, 1, 256, 512, 8, 128, 1><<<148, 512, SM0>>>(x, out, 0, 0, 1024);
    eqlin<32, 7, 32, 256, 1, 18, 3><<<444, 256, SM3>>>(x, out, 960, 86016, 7282);

    // join
    cudaEventRecord(evJoin, sB);
    cudaStreamWaitEvent(0, evJoin, 0);
}